// round 14
// baseline (speedup 1.0000x reference)
#include <cuda_runtime.h>
#include <cuda_bf16.h>
#include <math.h>

#define NPIX 8192
#define CDIM 256
#define HID  512
#define HH   64
#define WW   128
#define NHEAD 8
#define HD   32
#define KNB  7

#define STAGES 4
#define SROW   136

// natten tile config (16x32 pixels, pixel pairs, quarter channel split)
#define NTH 16
#define NTW 32
#define HALO_R 22
#define HALO_C 38
#define NPIXH (HALO_R * HALO_C)   // 836
#define NP    838

typedef unsigned long long u64;

// Scratch (static __device__ arrays; no allocation allowed)
__device__ __nv_bfloat16 g_xb[(size_t)CDIM * NPIX];
__device__ __nv_bfloat16 g_wqkvb[CDIM * 768];
__device__ __nv_bfloat16 g_wprojb[CDIM * CDIM];
__device__ __nv_bfloat16 g_wfc1b[CDIM * HID];
__device__ __nv_bfloat16 g_wfc2b[HID * CDIM];
__device__ __nv_bfloat16 g_qkv[(size_t)NPIX * 768];
__device__ __nv_bfloat16 g_aout[(size_t)CDIM * NPIX];
__device__ float         g_x1[(size_t)CDIM * NPIX];
__device__ __nv_bfloat16 g_x1b[(size_t)CDIM * NPIX];
__device__ __nv_bfloat16 g_h[(size_t)HID * NPIX];

__device__ __forceinline__ void cpa16(void* dst, const void* src) {
    unsigned d = (unsigned)__cvta_generic_to_shared(dst);
    asm volatile("cp.async.cg.shared.global [%0], [%1], 16;" :: "r"(d), "l"(src));
}

// packed f32x2 helpers
__device__ __forceinline__ u64 fma2(u64 a, u64 b, u64 c) {
    u64 d; asm("fma.rn.f32x2 %0, %1, %2, %3;" : "=l"(d) : "l"(a), "l"(b), "l"(c)); return d;
}
__device__ __forceinline__ u64 mul2(u64 a, u64 b) {
    u64 d; asm("mul.rn.f32x2 %0, %1, %2;" : "=l"(d) : "l"(a), "l"(b)); return d;
}
__device__ __forceinline__ u64 bfp(unsigned u) {
    unsigned lo = u << 16, hi = u & 0xffff0000u;
    u64 d; asm("mov.b64 %0, {%1, %2};" : "=l"(d) : "r"(lo), "r"(hi)); return d;
}
__device__ __forceinline__ u64 packf(float x, float y) {
    u64 d; asm("mov.b64 %0, {%1, %2};" : "=l"(d) : "f"(x), "f"(y)); return d;
}
__device__ __forceinline__ float2 unpk(u64 d) {
    float2 r; asm("mov.b64 {%0, %1}, %2;" : "=f"(r.x), "=f"(r.y) : "l"(d)); return r;
}

// ---------------------------------------------------------------------------
// Fused fp32->bf16 converter (x + 4 weights, one launch)
// ---------------------------------------------------------------------------
#define XB4   (CDIM * NPIX / 4)
#define NB_X   (XB4 / 256)               // 2048
#define NB_WQ  (CDIM * 768 / 4 / 256)    // 192
#define NB_WP  (CDIM * CDIM / 4 / 256)   // 64
#define NB_WF1 (CDIM * HID / 4 / 256)    // 128
#define NB_WF2 (HID * CDIM / 4 / 256)    // 128

__global__ __launch_bounds__(256) void convall(
    const float4* __restrict__ x,    uint2* __restrict__ xb,
    const float4* __restrict__ wq,   uint2* __restrict__ wqb,
    const float4* __restrict__ wp,   uint2* __restrict__ wpb,
    const float4* __restrict__ wf1,  uint2* __restrict__ wf1b,
    const float4* __restrict__ wf2,  uint2* __restrict__ wf2b)
{
    int b = blockIdx.x;
    const float4* src; uint2* dst;
    if (b < NB_X)                         { src = x;   dst = xb;   }
    else if ((b -= NB_X)  < NB_WQ)        { src = wq;  dst = wqb;  }
    else if ((b -= NB_WQ) < NB_WP)        { src = wp;  dst = wpb;  }
    else if ((b -= NB_WP) < NB_WF1)       { src = wf1; dst = wf1b; }
    else { b -= NB_WF1;                     src = wf2; dst = wf2b; }
    const int i = b * 256 + threadIdx.x;
    float4 v = src[i];
    __nv_bfloat162 lo = __float22bfloat162_rn(make_float2(v.x, v.y));
    __nv_bfloat162 hi = __float22bfloat162_rn(make_float2(v.z, v.w));
    uint2 o; o.x = *(unsigned*)&lo; o.y = *(unsigned*)&hi;
    dst[i] = o;
}

// ---------------------------------------------------------------------------
// bf16 tensor-core GEMM (EXACT R8 structure: 128x128x32, STAGES=4, NF=4)
// ---------------------------------------------------------------------------
template<int EPI>
__global__ __launch_bounds__(256, 2) void gemm_bf16(
    const __nv_bfloat16* __restrict__ R, const __nv_bfloat16* __restrict__ Cc,
    const float* __restrict__ bias, const float* __restrict__ res,
    void* __restrict__ OutV, __nv_bfloat16* __restrict__ Out2,
    int K, int ldR, int ldN)
{
    extern __shared__ __nv_bfloat16 smem[];
    __nv_bfloat16* Rs = smem;
    __nv_bfloat16* Cs = smem + STAGES * 32 * SROW;

    const int t    = threadIdx.x;
    const int lane = t & 31;
    const int wid  = t >> 5;
    const int wm   = (wid >> 2) * 64;
    const int wn   = (wid & 3) * 32;
    const int g    = lane >> 2;
    const int tg   = lane & 3;

    const int m0 = blockIdx.x * 128;
    const int n0 = blockIdx.y * 128;

    const int kr = t >> 4;
    const int ch = (t & 15) * 8;

    const __nv_bfloat16* Rg0 = R  + (size_t)kr * ldR + m0 + ch;
    const __nv_bfloat16* Rg1 = R  + (size_t)(kr + 16) * ldR + m0 + ch;
    const __nv_bfloat16* Cg0 = Cc + (size_t)kr * ldN + n0 + ch;
    const __nv_bfloat16* Cg1 = Cc + (size_t)(kr + 16) * ldN + n0 + ch;

    const int sub = lane >> 3, l8 = lane & 7;
    const int a_kr = ((sub >> 1) & 1) * 8 + l8;
    const int a_mo = (sub & 1) * 8;
    const int b_kr = (sub & 1) * 8 + l8;
    const int b_no = ((sub >> 1) & 1) * 8;

    float acc[4][4][4];
    #pragma unroll
    for (int im = 0; im < 4; im++)
        #pragma unroll
        for (int in = 0; in < 4; in++)
            #pragma unroll
            for (int r = 0; r < 4; r++) acc[im][in][r] = 0.f;

    auto issue_stage = [&](int s) {
        __nv_bfloat16* rb = Rs + s * (32 * SROW);
        __nv_bfloat16* cb = Cs + s * (32 * SROW);
        cpa16(rb + kr * SROW + ch, Rg0);
        cpa16(rb + (kr + 16) * SROW + ch, Rg1);
        cpa16(cb + kr * SROW + ch, Cg0);
        cpa16(cb + (kr + 16) * SROW + ch, Cg1);
        Rg0 += (size_t)32 * ldR; Rg1 += (size_t)32 * ldR;
        Cg0 += (size_t)32 * ldN; Cg1 += (size_t)32 * ldN;
    };

    const int niter = K >> 5;
    #pragma unroll
    for (int s = 0; s < STAGES - 1; s++) {
        issue_stage(s);
        asm volatile("cp.async.commit_group;");
    }

    int stage = 0, nxt = STAGES - 1;
    for (int it = 0; it < niter; it++) {
        asm volatile("cp.async.wait_group %0;" :: "n"(STAGES - 2));
        __syncthreads();
        if (it + STAGES - 1 < niter) issue_stage(nxt);
        asm volatile("cp.async.commit_group;");
        nxt = (nxt + 1 == STAGES) ? 0 : nxt + 1;

        const __nv_bfloat16* Rt = Rs + stage * (32 * SROW);
        const __nv_bfloat16* Ct = Cs + stage * (32 * SROW);
        #pragma unroll
        for (int ks = 0; ks < 2; ks++) {
            unsigned a[4][4], b[2][4];
            #pragma unroll
            for (int im = 0; im < 4; im++) {
                unsigned ad = (unsigned)__cvta_generic_to_shared(
                    Rt + (size_t)(ks * 16 + a_kr) * SROW + wm + im * 16 + a_mo);
                asm volatile(
                    "ldmatrix.sync.aligned.m8n8.x4.trans.shared.b16 {%0,%1,%2,%3},[%4];"
                    : "=r"(a[im][0]), "=r"(a[im][1]), "=r"(a[im][2]), "=r"(a[im][3])
                    : "r"(ad));
            }
            #pragma unroll
            for (int pr = 0; pr < 2; pr++) {
                unsigned bd = (unsigned)__cvta_generic_to_shared(
                    Ct + (size_t)(ks * 16 + b_kr) * SROW + wn + pr * 16 + b_no);
                asm volatile(
                    "ldmatrix.sync.aligned.m8n8.x4.trans.shared.b16 {%0,%1,%2,%3},[%4];"
                    : "=r"(b[pr][0]), "=r"(b[pr][1]), "=r"(b[pr][2]), "=r"(b[pr][3])
                    : "r"(bd));
            }
            #pragma unroll
            for (int im = 0; im < 4; im++)
                #pragma unroll
                for (int in = 0; in < 4; in++) {
                    const unsigned b0 = b[in >> 1][(in & 1) * 2];
                    const unsigned b1 = b[in >> 1][(in & 1) * 2 + 1];
                    asm volatile(
                        "mma.sync.aligned.m16n8k16.row.col.f32.bf16.bf16.f32 "
                        "{%0,%1,%2,%3},{%4,%5,%6,%7},{%8,%9},{%0,%1,%2,%3};"
                        : "+f"(acc[im][in][0]), "+f"(acc[im][in][1]),
                          "+f"(acc[im][in][2]), "+f"(acc[im][in][3])
                        : "r"(a[im][0]), "r"(a[im][1]), "r"(a[im][2]), "r"(a[im][3]),
                          "r"(b0), "r"(b1));
                }
        }
        stage = (stage + 1 == STAGES) ? 0 : stage + 1;
    }

    float* OutF = (float*)OutV;
    __nv_bfloat16* OutB = (__nv_bfloat16*)OutV;
    #pragma unroll
    for (int im = 0; im < 4; im++) {
        const int m = m0 + wm + im * 16 + g;
        #pragma unroll
        for (int in = 0; in < 4; in++) {
            const int n = n0 + wn + in * 8 + tg * 2;
            float v00 = acc[im][in][0], v01 = acc[im][in][1];
            float v10 = acc[im][in][2], v11 = acc[im][in][3];
            if (EPI == 0) {
                const float bn0 = bias[n], bn1 = bias[n + 1];
                v00 += bn0; v01 += bn1; v10 += bn0; v11 += bn1;
            } else {
                const float bm0 = bias[m], bm8 = bias[m + 8];
                v00 += bm0; v01 += bm0; v10 += bm8; v11 += bm8;
            }
            if (EPI == 1) {
                v00 = 0.5f * v00 * (1.f + erff(v00 * 0.70710678118654752f));
                v01 = 0.5f * v01 * (1.f + erff(v01 * 0.70710678118654752f));
                v10 = 0.5f * v10 * (1.f + erff(v10 * 0.70710678118654752f));
                v11 = 0.5f * v11 * (1.f + erff(v11 * 0.70710678118654752f));
            }
            if (EPI == 2 || EPI == 3) {
                float2 r0 = *(const float2*)&res[(size_t)m * ldN + n];
                float2 r1 = *(const float2*)&res[(size_t)(m + 8) * ldN + n];
                v00 += r0.x; v01 += r0.y; v10 += r1.x; v11 += r1.y;
            }
            if (EPI == 0 || EPI == 1) {
                __nv_bfloat162 o0 = __float22bfloat162_rn(make_float2(v00, v01));
                __nv_bfloat162 o1 = __float22bfloat162_rn(make_float2(v10, v11));
                *(__nv_bfloat162*)&OutB[(size_t)m * ldN + n] = o0;
                *(__nv_bfloat162*)&OutB[(size_t)(m + 8) * ldN + n] = o1;
            } else {
                float2 o0 = {v00, v01}, o1 = {v10, v11};
                *(float2*)&OutF[(size_t)m * ldN + n] = o0;
                *(float2*)&OutF[(size_t)(m + 8) * ldN + n] = o1;
                if (EPI == 2) {
                    __nv_bfloat162 p0 = __float22bfloat162_rn(make_float2(v00, v01));
                    __nv_bfloat162 p1 = __float22bfloat162_rn(make_float2(v10, v11));
                    *(__nv_bfloat162*)&Out2[(size_t)m * ldN + n] = p0;
                    *(__nv_bfloat162*)&Out2[(size_t)(m + 8) * ldN + n] = p1;
                }
            }
        }
    }
}

// ---------------------------------------------------------------------------
// Neighborhood attention v6: 16x32 tile, 1024 threads, vertical pixel pairs,
// QUARTER channel split (each thread owns 8 of 32 channels = one smem chunk).
// __launch_bounds__(1024) caps regs at 64/thread -> 32 warps/SM (2x v5 occ).
// QK dot reduced across the 4-lane quad with shfl_xor(1) + shfl_xor(2).
// ---------------------------------------------------------------------------
__global__ __launch_bounds__(1024) void natten6(
    const __nv_bfloat16* __restrict__ qkv, const float* __restrict__ rpb,
    __nv_bfloat16* __restrict__ aout)
{
    extern __shared__ uint4 sm[];
    uint4* ks = sm;                        // [4][NP]
    uint4* vs = sm + 4 * NP;               // [4][NP]
    float* rpb_s = (float*)(sm + 8 * NP);

    const int tid  = threadIdx.x;
    const int head = blockIdx.z;
    const int h0   = blockIdx.y * NTH;
    const int w0   = blockIdx.x * NTW;
    const int r0   = h0 - 3, c0 = w0 - 3;

    // Stage halo (zero-fill OOB)
    for (int idx = tid; idx < NPIXH; idx += 1024) {
        const int r  = idx / HALO_C;
        const int c  = idx - r * HALO_C;
        const int gh = r0 + r, gw = c0 + c;
        if (gh >= 0 && gh < HH && gw >= 0 && gw < WW) {
            const uint4* kp = (const uint4*)(qkv + (size_t)(gh * WW + gw) * 768 + 256 + head * HD);
            const uint4* vp = (const uint4*)(qkv + (size_t)(gh * WW + gw) * 768 + 512 + head * HD);
            #pragma unroll
            for (int s = 0; s < 4; s++) {
                ks[s * NP + idx] = kp[s];
                vs[s * NP + idx] = vp[s];
            }
        } else {
            uint4 z = {0u, 0u, 0u, 0u};
            #pragma unroll
            for (int s = 0; s < 4; s++) {
                ks[s * NP + idx] = z;
                vs[s * NP + idx] = z;
            }
        }
    }
    if (tid < 169) rpb_s[tid] = rpb[head * 169 + tid];
    __syncthreads();

    const int quart = tid & 3;             // channel quarter (8 channels)
    const int pair  = tid >> 2;            // 0..255
    const int py = pair >> 5;              // pair-row 0..7
    const int tx = pair & 31;
    const int hA = h0 + py * 2, hB = hA + 1;
    const int w  = w0 + tx;
    const int shA = min(max(hA - 3, 0), HH - KNB);
    const int shB = min(max(hB - 3, 0), HH - KNB);
    const int delta = shB - shA;           // 0 or 1
    const int sw  = min(max(w - 3, 0), WW - KNB);
    const int srow = shA - r0, scol = sw - c0;
    const int bhA = shA - hA + 6;
    const int bhB = shB - hB + 6;
    const int bw  = sw - w + 6;

    // q (8 channels, scale folded in)
    u64 qA[4], qB[4];
    {
        const float scale = 0.17677669529663687f;
        const u64 sc2 = packf(scale, scale);
        const uint4 ua = *(const uint4*)(qkv + (size_t)(hA * WW + w) * 768 + head * HD + quart * 8);
        const uint4 ub = *(const uint4*)(qkv + (size_t)(hB * WW + w) * 768 + head * HD + quart * 8);
        qA[0] = mul2(bfp(ua.x), sc2); qA[1] = mul2(bfp(ua.y), sc2);
        qA[2] = mul2(bfp(ua.z), sc2); qA[3] = mul2(bfp(ua.w), sc2);
        qB[0] = mul2(bfp(ub.x), sc2); qB[1] = mul2(bfp(ub.y), sc2);
        qB[2] = mul2(bfp(ub.z), sc2); qB[3] = mul2(bfp(ub.w), sc2);
    }

    u64 accA[4], accB[4];
    #pragma unroll
    for (int t = 0; t < 4; t++) { accA[t] = 0ull; accB[t] = 0ull; }
    float lsA = 0.f, lsB = 0.f;

    const uint4* ksq = ks + quart * NP;
    const uint4* vsq = vs + quart * NP;

    for (int i = 0; i < 8; i++) {
        const bool vA = (i < 7);
        const bool vB = (i >= delta) && (i < 7 + delta);
        const int rowA = min(bhA + i, 12);
        const int rowB = max(0, min(bhB + i - delta, 12));
        const float* rA = rpb_s + rowA * 13 + bw;
        const float* rB = rpb_s + rowB * 13 + bw;
        const int prow = (srow + i) * HALO_C + scol;
        #pragma unroll
        for (int j = 0; j < 7; j++) {
            const int p = prow + j;
            uint4 kl = ksq[p];
            const unsigned* kw = (const unsigned*)&kl;
            u64 dA = 0ull, dB = 0ull;
            #pragma unroll
            for (int t = 0; t < 4; t++) {
                const u64 kk = bfp(kw[t]);
                dA = fma2(qA[t], kk, dA);
                dB = fma2(qB[t], kk, dB);
            }
            float2 fA = unpk(dA);
            float2 fB = unpk(dB);
            float sA = fA.x + fA.y;
            float sB = fB.x + fB.y;
            sA += __shfl_xor_sync(0xffffffffu, sA, 1);
            sB += __shfl_xor_sync(0xffffffffu, sB, 1);
            sA += __shfl_xor_sync(0xffffffffu, sA, 2);
            sB += __shfl_xor_sync(0xffffffffu, sB, 2);
            const float eA = vA ? __expf(sA + rA[j]) : 0.f;
            const float eB = vB ? __expf(sB + rB[j]) : 0.f;
            lsA += eA; lsB += eB;
            const u64 eA2 = packf(eA, eA);
            const u64 eB2 = packf(eB, eB);
            uint4 vl = vsq[p];
            const unsigned* vw = (const unsigned*)&vl;
            #pragma unroll
            for (int t = 0; t < 4; t++) {
                const u64 vv = bfp(vw[t]);
                accA[t] = fma2(eA2, vv, accA[t]);
                accB[t] = fma2(eB2, vv, accB[t]);
            }
        }
    }

    const float ivA = 1.f / lsA;
    const float ivB = 1.f / lsB;
    const int pA = hA * WW + w;
    const int pB = hB * WW + w;
    const int cbase = head * HD + quart * 8;
    #pragma unroll
    for (int t = 0; t < 4; t++) {
        float2 a = unpk(accA[t]);
        float2 b = unpk(accB[t]);
        const size_t c0o = (size_t)(cbase + 2 * t) * NPIX;
        const size_t c1o = (size_t)(cbase + 2 * t + 1) * NPIX;
        aout[c0o + pA] = __float2bfloat16(a.x * ivA);
        aout[c1o + pA] = __float2bfloat16(a.y * ivA);
        aout[c0o + pB] = __float2bfloat16(b.x * ivB);
        aout[c1o + pB] = __float2bfloat16(b.y * ivB);
    }
}

// ---------------------------------------------------------------------------
extern "C" void kernel_launch(void* const* d_in, const int* in_sizes, int n_in,
                              void* d_out, int out_size)
{
    const float* x      = (const float*)d_in[0];
    const float* w_qkv  = (const float*)d_in[1];
    const float* b_qkv  = (const float*)d_in[2];
    const float* rpb    = (const float*)d_in[3];
    const float* w_proj = (const float*)d_in[4];
    const float* b_proj = (const float*)d_in[5];
    const float* w_fc1  = (const float*)d_in[6];
    const float* b_fc1  = (const float*)d_in[7];
    const float* w_fc2  = (const float*)d_in[8];
    const float* b_fc2  = (const float*)d_in[9];
    float* y = (float*)d_out;

    __nv_bfloat16 *xb, *wqkvb, *wprojb, *wfc1b, *wfc2b, *qkv, *aout, *x1b, *hbuf;
    float *x1;
    cudaGetSymbolAddress((void**)&xb,    g_xb);
    cudaGetSymbolAddress((void**)&wqkvb, g_wqkvb);
    cudaGetSymbolAddress((void**)&wprojb,g_wprojb);
    cudaGetSymbolAddress((void**)&wfc1b, g_wfc1b);
    cudaGetSymbolAddress((void**)&wfc2b, g_wfc2b);
    cudaGetSymbolAddress((void**)&qkv,   g_qkv);
    cudaGetSymbolAddress((void**)&aout,  g_aout);
    cudaGetSymbolAddress((void**)&x1,    g_x1);
    cudaGetSymbolAddress((void**)&x1b,   g_x1b);
    cudaGetSymbolAddress((void**)&hbuf,  g_h);

    const int SMEM = STAGES * 32 * SROW * 2 * 2;   // 69632 B
    cudaFuncSetAttribute(gemm_bf16<0>, cudaFuncAttributeMaxDynamicSharedMemorySize, SMEM);
    cudaFuncSetAttribute(gemm_bf16<1>, cudaFuncAttributeMaxDynamicSharedMemorySize, SMEM);
    cudaFuncSetAttribute(gemm_bf16<2>, cudaFuncAttributeMaxDynamicSharedMemorySize, SMEM);
    cudaFuncSetAttribute(gemm_bf16<3>, cudaFuncAttributeMaxDynamicSharedMemorySize, SMEM);

    const int NSMEM = 8 * NP * 16 + 169 * 4 + 16;   // ~107.9 KB
    cudaFuncSetAttribute(natten6, cudaFuncAttributeMaxDynamicSharedMemorySize, NSMEM);

    // 0) convert x + all weights to bf16 (one launch)
    convall<<<NB_X + NB_WQ + NB_WP + NB_WF1 + NB_WF2, 256>>>(
        (const float4*)x,      (uint2*)xb,
        (const float4*)w_qkv,  (uint2*)wqkvb,
        (const float4*)w_proj, (uint2*)wprojb,
        (const float4*)w_fc1,  (uint2*)wfc1b,
        (const float4*)w_fc2,  (uint2*)wfc2b);

    // 1) qkv[p][768] = x^T @ w_qkv + b_qkv  (384 blocks)
    gemm_bf16<0><<<dim3(NPIX / 128, 768 / 128), 256, SMEM>>>(
        xb, wqkvb, b_qkv, nullptr, qkv, nullptr, CDIM, NPIX, 768);

    // 2) neighborhood attention (quarter-split, 32 warps/SM) -> aout bf16
    natten6<<<dim3(WW / NTW, HH / NTH, NHEAD), 1024, NSMEM>>>(qkv, rpb, aout);

    // 3) x1 = w_proj^T(aout) + b_proj + x
    gemm_bf16<2><<<dim3(CDIM / 128, NPIX / 128), 256, SMEM>>>(
        wprojb, aout, b_proj, x, x1, x1b, CDIM, CDIM, NPIX);

    // 4) h = gelu(fc1(x1))
    gemm_bf16<1><<<dim3(HID / 128, NPIX / 128), 256, SMEM>>>(
        wfc1b, x1b, b_fc1, nullptr, hbuf, nullptr, CDIM, HID, NPIX);

    // 5) y = fc2(h) + b_fc2 + x1
    gemm_bf16<3><<<dim3(CDIM / 128, NPIX / 128), 256, SMEM>>>(
        wfc2b, hbuf, b_fc2, x1, y, nullptr, HID, CDIM, NPIX);
}

// round 15
// speedup vs baseline: 1.0523x; 1.0523x over previous
#include <cuda_runtime.h>
#include <cuda_bf16.h>
#include <math.h>

#define NPIX 8192
#define CDIM 256
#define HID  512
#define HH   64
#define WW   128
#define NHEAD 8
#define HD   32
#define KNB  7

#define STAGES 4
#define SROW   136

// natten tile config (R8 natten5)
#define NTH 16
#define NTW 32
#define HALO_R 22
#define HALO_C 38
#define NPIXH (HALO_R * HALO_C)   // 836
#define NP    838

typedef unsigned long long u64;

// Scratch (static __device__ arrays; no allocation allowed)
__device__ __nv_bfloat16 g_xb[(size_t)CDIM * NPIX];
__device__ __nv_bfloat16 g_wqkvb[CDIM * 768];
__device__ __nv_bfloat16 g_wprojb[CDIM * CDIM];
__device__ __nv_bfloat16 g_wfc1b[CDIM * HID];
__device__ __nv_bfloat16 g_wfc2b[HID * CDIM];
__device__ __nv_bfloat16 g_qkv[(size_t)NPIX * 768];
__device__ __nv_bfloat16 g_aout[(size_t)CDIM * NPIX];
__device__ float         g_x1[(size_t)CDIM * NPIX];
__device__ __nv_bfloat16 g_x1b[(size_t)CDIM * NPIX];
__device__ __nv_bfloat16 g_h[(size_t)HID * NPIX];

__device__ __forceinline__ void cpa16(void* dst, const void* src) {
    unsigned d = (unsigned)__cvta_generic_to_shared(dst);
    asm volatile("cp.async.cg.shared.global [%0], [%1], 16;" :: "r"(d), "l"(src));
}

// packed f32x2 helpers
__device__ __forceinline__ u64 fma2(u64 a, u64 b, u64 c) {
    u64 d; asm("fma.rn.f32x2 %0, %1, %2, %3;" : "=l"(d) : "l"(a), "l"(b), "l"(c)); return d;
}
__device__ __forceinline__ u64 mul2(u64 a, u64 b) {
    u64 d; asm("mul.rn.f32x2 %0, %1, %2;" : "=l"(d) : "l"(a), "l"(b)); return d;
}
__device__ __forceinline__ u64 bfp(unsigned u) {
    unsigned lo = u << 16, hi = u & 0xffff0000u;
    u64 d; asm("mov.b64 %0, {%1, %2};" : "=l"(d) : "r"(lo), "r"(hi)); return d;
}
__device__ __forceinline__ u64 packf(float x, float y) {
    u64 d; asm("mov.b64 %0, {%1, %2};" : "=l"(d) : "f"(x), "f"(y)); return d;
}
__device__ __forceinline__ float2 unpk(u64 d) {
    float2 r; asm("mov.b64 {%0, %1}, %2;" : "=f"(r.x), "=f"(r.y) : "l"(d)); return r;
}

// ---------------------------------------------------------------------------
// Fused fp32->bf16 converter, 2 float4 per thread (converter is launch-bound,
// not BW-bound: halve the grid, double ILP).
// ---------------------------------------------------------------------------
#define NB2_X   (CDIM * NPIX / 4 / 512)   // 1024
#define NB2_WQ  (CDIM * 768 / 4 / 512)    // 96
#define NB2_WP  (CDIM * CDIM / 4 / 512)   // 32
#define NB2_WF1 (CDIM * HID / 4 / 512)    // 64
#define NB2_WF2 (HID * CDIM / 4 / 512)    // 64

__global__ __launch_bounds__(256) void convall(
    const float4* __restrict__ x,    uint2* __restrict__ xb,
    const float4* __restrict__ wq,   uint2* __restrict__ wqb,
    const float4* __restrict__ wp,   uint2* __restrict__ wpb,
    const float4* __restrict__ wf1,  uint2* __restrict__ wf1b,
    const float4* __restrict__ wf2,  uint2* __restrict__ wf2b)
{
    int b = blockIdx.x;
    const float4* src; uint2* dst;
    if (b < NB2_X)                          { src = x;   dst = xb;   }
    else if ((b -= NB2_X)  < NB2_WQ)        { src = wq;  dst = wqb;  }
    else if ((b -= NB2_WQ) < NB2_WP)        { src = wp;  dst = wpb;  }
    else if ((b -= NB2_WP) < NB2_WF1)       { src = wf1; dst = wf1b; }
    else { b -= NB2_WF1;                      src = wf2; dst = wf2b; }
    const int i0 = b * 512 + threadIdx.x;
    const int i1 = i0 + 256;
    float4 v0 = src[i0];
    float4 v1 = src[i1];
    __nv_bfloat162 a0 = __float22bfloat162_rn(make_float2(v0.x, v0.y));
    __nv_bfloat162 a1 = __float22bfloat162_rn(make_float2(v0.z, v0.w));
    __nv_bfloat162 b0 = __float22bfloat162_rn(make_float2(v1.x, v1.y));
    __nv_bfloat162 b1 = __float22bfloat162_rn(make_float2(v1.z, v1.w));
    uint2 o0; o0.x = *(unsigned*)&a0; o0.y = *(unsigned*)&a1;
    uint2 o1; o1.x = *(unsigned*)&b0; o1.y = *(unsigned*)&b1;
    dst[i0] = o0;
    dst[i1] = o1;
}

// ---------------------------------------------------------------------------
// bf16 tensor-core GEMM (EXACT R8 structure: 128x128x32, STAGES=4, NF=4)
// ---------------------------------------------------------------------------
template<int EPI>
__global__ __launch_bounds__(256, 2) void gemm_bf16(
    const __nv_bfloat16* __restrict__ R, const __nv_bfloat16* __restrict__ Cc,
    const float* __restrict__ bias, const float* __restrict__ res,
    void* __restrict__ OutV, __nv_bfloat16* __restrict__ Out2,
    int K, int ldR, int ldN)
{
    extern __shared__ __nv_bfloat16 smem[];
    __nv_bfloat16* Rs = smem;
    __nv_bfloat16* Cs = smem + STAGES * 32 * SROW;

    const int t    = threadIdx.x;
    const int lane = t & 31;
    const int wid  = t >> 5;
    const int wm   = (wid >> 2) * 64;
    const int wn   = (wid & 3) * 32;
    const int g    = lane >> 2;
    const int tg   = lane & 3;

    const int m0 = blockIdx.x * 128;
    const int n0 = blockIdx.y * 128;

    const int kr = t >> 4;
    const int ch = (t & 15) * 8;

    const __nv_bfloat16* Rg0 = R  + (size_t)kr * ldR + m0 + ch;
    const __nv_bfloat16* Rg1 = R  + (size_t)(kr + 16) * ldR + m0 + ch;
    const __nv_bfloat16* Cg0 = Cc + (size_t)kr * ldN + n0 + ch;
    const __nv_bfloat16* Cg1 = Cc + (size_t)(kr + 16) * ldN + n0 + ch;

    const int sub = lane >> 3, l8 = lane & 7;
    const int a_kr = ((sub >> 1) & 1) * 8 + l8;
    const int a_mo = (sub & 1) * 8;
    const int b_kr = (sub & 1) * 8 + l8;
    const int b_no = ((sub >> 1) & 1) * 8;

    float acc[4][4][4];
    #pragma unroll
    for (int im = 0; im < 4; im++)
        #pragma unroll
        for (int in = 0; in < 4; in++)
            #pragma unroll
            for (int r = 0; r < 4; r++) acc[im][in][r] = 0.f;

    auto issue_stage = [&](int s) {
        __nv_bfloat16* rb = Rs + s * (32 * SROW);
        __nv_bfloat16* cb = Cs + s * (32 * SROW);
        cpa16(rb + kr * SROW + ch, Rg0);
        cpa16(rb + (kr + 16) * SROW + ch, Rg1);
        cpa16(cb + kr * SROW + ch, Cg0);
        cpa16(cb + (kr + 16) * SROW + ch, Cg1);
        Rg0 += (size_t)32 * ldR; Rg1 += (size_t)32 * ldR;
        Cg0 += (size_t)32 * ldN; Cg1 += (size_t)32 * ldN;
    };

    const int niter = K >> 5;
    #pragma unroll
    for (int s = 0; s < STAGES - 1; s++) {
        issue_stage(s);
        asm volatile("cp.async.commit_group;");
    }

    int stage = 0, nxt = STAGES - 1;
    for (int it = 0; it < niter; it++) {
        asm volatile("cp.async.wait_group %0;" :: "n"(STAGES - 2));
        __syncthreads();
        if (it + STAGES - 1 < niter) issue_stage(nxt);
        asm volatile("cp.async.commit_group;");
        nxt = (nxt + 1 == STAGES) ? 0 : nxt + 1;

        const __nv_bfloat16* Rt = Rs + stage * (32 * SROW);
        const __nv_bfloat16* Ct = Cs + stage * (32 * SROW);
        #pragma unroll
        for (int ks = 0; ks < 2; ks++) {
            unsigned a[4][4], b[2][4];
            #pragma unroll
            for (int im = 0; im < 4; im++) {
                unsigned ad = (unsigned)__cvta_generic_to_shared(
                    Rt + (size_t)(ks * 16 + a_kr) * SROW + wm + im * 16 + a_mo);
                asm volatile(
                    "ldmatrix.sync.aligned.m8n8.x4.trans.shared.b16 {%0,%1,%2,%3},[%4];"
                    : "=r"(a[im][0]), "=r"(a[im][1]), "=r"(a[im][2]), "=r"(a[im][3])
                    : "r"(ad));
            }
            #pragma unroll
            for (int pr = 0; pr < 2; pr++) {
                unsigned bd = (unsigned)__cvta_generic_to_shared(
                    Ct + (size_t)(ks * 16 + b_kr) * SROW + wn + pr * 16 + b_no);
                asm volatile(
                    "ldmatrix.sync.aligned.m8n8.x4.trans.shared.b16 {%0,%1,%2,%3},[%4];"
                    : "=r"(b[pr][0]), "=r"(b[pr][1]), "=r"(b[pr][2]), "=r"(b[pr][3])
                    : "r"(bd));
            }
            #pragma unroll
            for (int im = 0; im < 4; im++)
                #pragma unroll
                for (int in = 0; in < 4; in++) {
                    const unsigned b0 = b[in >> 1][(in & 1) * 2];
                    const unsigned b1 = b[in >> 1][(in & 1) * 2 + 1];
                    asm volatile(
                        "mma.sync.aligned.m16n8k16.row.col.f32.bf16.bf16.f32 "
                        "{%0,%1,%2,%3},{%4,%5,%6,%7},{%8,%9},{%0,%1,%2,%3};"
                        : "+f"(acc[im][in][0]), "+f"(acc[im][in][1]),
                          "+f"(acc[im][in][2]), "+f"(acc[im][in][3])
                        : "r"(a[im][0]), "r"(a[im][1]), "r"(a[im][2]), "r"(a[im][3]),
                          "r"(b0), "r"(b1));
                }
        }
        stage = (stage + 1 == STAGES) ? 0 : stage + 1;
    }

    float* OutF = (float*)OutV;
    __nv_bfloat16* OutB = (__nv_bfloat16*)OutV;
    #pragma unroll
    for (int im = 0; im < 4; im++) {
        const int m = m0 + wm + im * 16 + g;
        #pragma unroll
        for (int in = 0; in < 4; in++) {
            const int n = n0 + wn + in * 8 + tg * 2;
            float v00 = acc[im][in][0], v01 = acc[im][in][1];
            float v10 = acc[im][in][2], v11 = acc[im][in][3];
            if (EPI == 0) {
                const float bn0 = bias[n], bn1 = bias[n + 1];
                v00 += bn0; v01 += bn1; v10 += bn0; v11 += bn1;
            } else {
                const float bm0 = bias[m], bm8 = bias[m + 8];
                v00 += bm0; v01 += bm0; v10 += bm8; v11 += bm8;
            }
            if (EPI == 1) {
                v00 = 0.5f * v00 * (1.f + erff(v00 * 0.70710678118654752f));
                v01 = 0.5f * v01 * (1.f + erff(v01 * 0.70710678118654752f));
                v10 = 0.5f * v10 * (1.f + erff(v10 * 0.70710678118654752f));
                v11 = 0.5f * v11 * (1.f + erff(v11 * 0.70710678118654752f));
            }
            if (EPI == 2 || EPI == 3) {
                float2 r0 = *(const float2*)&res[(size_t)m * ldN + n];
                float2 r1 = *(const float2*)&res[(size_t)(m + 8) * ldN + n];
                v00 += r0.x; v01 += r0.y; v10 += r1.x; v11 += r1.y;
            }
            if (EPI == 0 || EPI == 1) {
                __nv_bfloat162 o0 = __float22bfloat162_rn(make_float2(v00, v01));
                __nv_bfloat162 o1 = __float22bfloat162_rn(make_float2(v10, v11));
                *(__nv_bfloat162*)&OutB[(size_t)m * ldN + n] = o0;
                *(__nv_bfloat162*)&OutB[(size_t)(m + 8) * ldN + n] = o1;
            } else {
                float2 o0 = {v00, v01}, o1 = {v10, v11};
                *(float2*)&OutF[(size_t)m * ldN + n] = o0;
                *(float2*)&OutF[(size_t)(m + 8) * ldN + n] = o1;
                if (EPI == 2) {
                    __nv_bfloat162 p0 = __float22bfloat162_rn(make_float2(v00, v01));
                    __nv_bfloat162 p1 = __float22bfloat162_rn(make_float2(v10, v11));
                    *(__nv_bfloat162*)&Out2[(size_t)m * ldN + n] = p0;
                    *(__nv_bfloat162*)&Out2[(size_t)(m + 8) * ldN + n] = p1;
                }
            }
        }
    }
}

// ---------------------------------------------------------------------------
// Neighborhood attention v5b: identical hot loop to R8's natten5; only the
// epilogue changed — results staged through (now-dead) k/v smem as a
// [32 ch][512 px] bf16 tile, then stored with uint4 (64B-segment) STGs
// instead of 32 scattered 2B STGs per thread.
// ---------------------------------------------------------------------------
__global__ __launch_bounds__(512) void natten5(
    const __nv_bfloat16* __restrict__ qkv, const float* __restrict__ rpb,
    __nv_bfloat16* __restrict__ aout)
{
    extern __shared__ uint4 sm[];
    uint4* ks = sm;
    uint4* vs = sm + 4 * NP;
    float* rpb_s = (float*)(sm + 8 * NP);

    const int tid  = threadIdx.x;
    const int head = blockIdx.z;
    const int h0   = blockIdx.y * NTH;
    const int w0   = blockIdx.x * NTW;
    const int r0   = h0 - 3, c0 = w0 - 3;

    for (int idx = tid; idx < NPIXH; idx += 512) {
        const int r  = idx / HALO_C;
        const int c  = idx - r * HALO_C;
        const int gh = r0 + r, gw = c0 + c;
        if (gh >= 0 && gh < HH && gw >= 0 && gw < WW) {
            const uint4* kp = (const uint4*)(qkv + (size_t)(gh * WW + gw) * 768 + 256 + head * HD);
            const uint4* vp = (const uint4*)(qkv + (size_t)(gh * WW + gw) * 768 + 512 + head * HD);
            #pragma unroll
            for (int s = 0; s < 4; s++) {
                ks[s * NP + idx] = kp[s];
                vs[s * NP + idx] = vp[s];
            }
        } else {
            uint4 z = {0u, 0u, 0u, 0u};
            #pragma unroll
            for (int s = 0; s < 4; s++) {
                ks[s * NP + idx] = z;
                vs[s * NP + idx] = z;
            }
        }
    }
    if (tid < 169) rpb_s[tid] = rpb[head * 169 + tid];
    __syncthreads();

    const int half = tid & 1;
    const int pair = tid >> 1;
    const int py = pair >> 5;
    const int tx = pair & 31;
    const int hA = h0 + py * 2, hB = hA + 1;
    const int w  = w0 + tx;
    const int shA = min(max(hA - 3, 0), HH - KNB);
    const int shB = min(max(hB - 3, 0), HH - KNB);
    const int delta = shB - shA;
    const int sw  = min(max(w - 3, 0), WW - KNB);
    const int srow = shA - r0, scol = sw - c0;
    const int bhA = shA - hA + 6;
    const int bhB = shB - hB + 6;
    const int bw  = sw - w + 6;
    const int c2  = half * 2;

    u64 qA[8], qB[8];
    {
        const float scale = 0.17677669529663687f;
        const u64 sc2 = packf(scale, scale);
        const uint4* qpA = (const uint4*)(qkv + (size_t)(hA * WW + w) * 768 + head * HD + half * 16);
        const uint4* qpB = (const uint4*)(qkv + (size_t)(hB * WW + w) * 768 + head * HD + half * 16);
        #pragma unroll
        for (int s = 0; s < 2; s++) {
            uint4 ua = qpA[s], ub = qpB[s];
            qA[s * 4 + 0] = mul2(bfp(ua.x), sc2);
            qA[s * 4 + 1] = mul2(bfp(ua.y), sc2);
            qA[s * 4 + 2] = mul2(bfp(ua.z), sc2);
            qA[s * 4 + 3] = mul2(bfp(ua.w), sc2);
            qB[s * 4 + 0] = mul2(bfp(ub.x), sc2);
            qB[s * 4 + 1] = mul2(bfp(ub.y), sc2);
            qB[s * 4 + 2] = mul2(bfp(ub.z), sc2);
            qB[s * 4 + 3] = mul2(bfp(ub.w), sc2);
        }
    }

    u64 accA[8], accB[8];
    #pragma unroll
    for (int t = 0; t < 8; t++) { accA[t] = 0ull; accB[t] = 0ull; }
    float lsA = 0.f, lsB = 0.f;

    for (int i = 0; i < 8; i++) {
        const bool vA = (i < 7);
        const bool vB = (i >= delta) && (i < 7 + delta);
        const int rowA = min(bhA + i, 12);
        const int rowB = max(0, min(bhB + i - delta, 12));
        const float* rA = rpb_s + rowA * 13 + bw;
        const float* rB = rpb_s + rowB * 13 + bw;
        const int prow = (srow + i) * HALO_C + scol;
        #pragma unroll
        for (int j = 0; j < 7; j++) {
            const int p = prow + j;
            uint4 k0 = ks[c2 * NP + p];
            uint4 k1 = ks[(c2 + 1) * NP + p];
            const unsigned* kw0 = (const unsigned*)&k0;
            const unsigned* kw1 = (const unsigned*)&k1;
            u64 dA = 0ull, dB = 0ull;
            #pragma unroll
            for (int t = 0; t < 4; t++) {
                const u64 ka = bfp(kw0[t]);
                const u64 kb = bfp(kw1[t]);
                dA = fma2(qA[t],     ka, dA);
                dA = fma2(qA[t + 4], kb, dA);
                dB = fma2(qB[t],     ka, dB);
                dB = fma2(qB[t + 4], kb, dB);
            }
            float2 fA = unpk(dA);
            float2 fB = unpk(dB);
            float sA = fA.x + fA.y;
            float sB = fB.x + fB.y;
            sA += __shfl_xor_sync(0xffffffffu, sA, 1);
            sB += __shfl_xor_sync(0xffffffffu, sB, 1);
            const float eA = vA ? __expf(sA + rA[j]) : 0.f;
            const float eB = vB ? __expf(sB + rB[j]) : 0.f;
            lsA += eA; lsB += eB;
            const u64 eA2 = packf(eA, eA);
            const u64 eB2 = packf(eB, eB);
            uint4 v0 = vs[c2 * NP + p];
            uint4 v1 = vs[(c2 + 1) * NP + p];
            const unsigned* vw0 = (const unsigned*)&v0;
            const unsigned* vw1 = (const unsigned*)&v1;
            #pragma unroll
            for (int t = 0; t < 4; t++) {
                const u64 va = bfp(vw0[t]);
                const u64 vb = bfp(vw1[t]);
                accA[t]     = fma2(eA2, va, accA[t]);
                accA[t + 4] = fma2(eA2, vb, accA[t + 4]);
                accB[t]     = fma2(eB2, va, accB[t]);
                accB[t + 4] = fma2(eB2, vb, accB[t + 4]);
            }
        }
    }

    const float ivA = 1.f / lsA;
    const float ivB = 1.f / lsB;

    // ---- staged epilogue: k/v smem is dead now; reuse as [32][512] bf16 ----
    __syncthreads();
    __nv_bfloat16* sout = (__nv_bfloat16*)sm;
    {
        const int lpA = (py * 2) * NTW + tx;       // local pixel of hA
        const int lpB = lpA + NTW;                 // local pixel of hB
        const int cb = half * 16;
        #pragma unroll
        for (int t = 0; t < 8; t++) {
            float2 a = unpk(accA[t]);
            float2 b = unpk(accB[t]);
            sout[(cb + 2 * t)     * 512 + lpA] = __float2bfloat16(a.x * ivA);
            sout[(cb + 2 * t + 1) * 512 + lpA] = __float2bfloat16(a.y * ivA);
            sout[(cb + 2 * t)     * 512 + lpB] = __float2bfloat16(b.x * ivB);
            sout[(cb + 2 * t + 1) * 512 + lpB] = __float2bfloat16(b.y * ivB);
        }
    }
    __syncthreads();

    // coalesced store: 2048 uint4 (32 ch x 64 uint4), 4 per thread
    #pragma unroll
    for (int s = 0; s < 4; s++) {
        const int idx = s * 512 + tid;
        const int c   = idx >> 6;                  // channel 0..31
        const int off = idx & 63;                  // uint4 within channel
        const int lp  = off * 8;
        const int lh  = lp >> 5, lw = lp & 31;
        uint4 val = ((const uint4*)(sout + c * 512))[off];
        *(uint4*)&aout[(size_t)(head * HD + c) * NPIX + (h0 + lh) * WW + w0 + lw] = val;
    }
}

// ---------------------------------------------------------------------------
extern "C" void kernel_launch(void* const* d_in, const int* in_sizes, int n_in,
                              void* d_out, int out_size)
{
    const float* x      = (const float*)d_in[0];
    const float* w_qkv  = (const float*)d_in[1];
    const float* b_qkv  = (const float*)d_in[2];
    const float* rpb    = (const float*)d_in[3];
    const float* w_proj = (const float*)d_in[4];
    const float* b_proj = (const float*)d_in[5];
    const float* w_fc1  = (const float*)d_in[6];
    const float* b_fc1  = (const float*)d_in[7];
    const float* w_fc2  = (const float*)d_in[8];
    const float* b_fc2  = (const float*)d_in[9];
    float* y = (float*)d_out;

    __nv_bfloat16 *xb, *wqkvb, *wprojb, *wfc1b, *wfc2b, *qkv, *aout, *x1b, *hbuf;
    float *x1;
    cudaGetSymbolAddress((void**)&xb,    g_xb);
    cudaGetSymbolAddress((void**)&wqkvb, g_wqkvb);
    cudaGetSymbolAddress((void**)&wprojb,g_wprojb);
    cudaGetSymbolAddress((void**)&wfc1b, g_wfc1b);
    cudaGetSymbolAddress((void**)&wfc2b, g_wfc2b);
    cudaGetSymbolAddress((void**)&qkv,   g_qkv);
    cudaGetSymbolAddress((void**)&aout,  g_aout);
    cudaGetSymbolAddress((void**)&x1,    g_x1);
    cudaGetSymbolAddress((void**)&x1b,   g_x1b);
    cudaGetSymbolAddress((void**)&hbuf,  g_h);

    const int SMEM = STAGES * 32 * SROW * 2 * 2;   // 69632 B
    cudaFuncSetAttribute(gemm_bf16<0>, cudaFuncAttributeMaxDynamicSharedMemorySize, SMEM);
    cudaFuncSetAttribute(gemm_bf16<1>, cudaFuncAttributeMaxDynamicSharedMemorySize, SMEM);
    cudaFuncSetAttribute(gemm_bf16<2>, cudaFuncAttributeMaxDynamicSharedMemorySize, SMEM);
    cudaFuncSetAttribute(gemm_bf16<3>, cudaFuncAttributeMaxDynamicSharedMemorySize, SMEM);

    const int NSMEM = 8 * NP * 16 + 169 * 4 + 16;   // ~107.9 KB
    cudaFuncSetAttribute(natten5, cudaFuncAttributeMaxDynamicSharedMemorySize, NSMEM);

    // 0) convert x + all weights to bf16 (one launch, 2 float4/thread)
    convall<<<NB2_X + NB2_WQ + NB2_WP + NB2_WF1 + NB2_WF2, 256>>>(
        (const float4*)x,      (uint2*)xb,
        (const float4*)w_qkv,  (uint2*)wqkvb,
        (const float4*)w_proj, (uint2*)wprojb,
        (const float4*)w_fc1,  (uint2*)wfc1b,
        (const float4*)w_fc2,  (uint2*)wfc2b);

    // 1) qkv[p][768] = x^T @ w_qkv + b_qkv  (384 blocks)
    gemm_bf16<0><<<dim3(NPIX / 128, 768 / 128), 256, SMEM>>>(
        xb, wqkvb, b_qkv, nullptr, qkv, nullptr, CDIM, NPIX, 768);

    // 2) neighborhood attention -> aout [256][N] bf16 (coalesced epilogue)
    natten5<<<dim3(WW / NTW, HH / NTH, NHEAD), 512, NSMEM>>>(qkv, rpb, aout);

    // 3) x1 = w_proj^T(aout) + b_proj + x
    gemm_bf16<2><<<dim3(CDIM / 128, NPIX / 128), 256, SMEM>>>(
        wprojb, aout, b_proj, x, x1, x1b, CDIM, CDIM, NPIX);

    // 4) h = gelu(fc1(x1))
    gemm_bf16<1><<<dim3(HID / 128, NPIX / 128), 256, SMEM>>>(
        wfc1b, x1b, b_fc1, nullptr, hbuf, nullptr, CDIM, HID, NPIX);

    // 5) y = fc2(h) + b_fc2 + x1
    gemm_bf16<3><<<dim3(CDIM / 128, NPIX / 128), 256, SMEM>>>(
        wfc2b, hbuf, b_fc2, x1, y, nullptr, HID, CDIM, NPIX);
}